// round 1
// baseline (speedup 1.0000x reference)
#include <cuda_runtime.h>
#include <stdint.h>

// Instant-NGP hash-grid interpolation encoding.
// B=262144 points, DIM=3, L=16 levels, T=19 (2^19-entry tables), F=2 features.
// out[b, l*2 + f] = sum_{v=0..7} w_v * tables[l, hash(corner_v) & MASK, f]

#define NB   262144
#define NL   16
#define TBITS 19
#define TMASK ((1u << TBITS) - 1u)

// res_l = floor(16 * (512/16)^(l/15))  (standard NGP geometric progression)
__constant__ float c_res[NL] = {
    16.f, 20.f, 25.f, 32.f, 40.f, 50.f, 64.f, 80.f,
    101.f, 128.f, 161.f, 203.f, 256.f, 322.f, 406.f, 512.f
};

__global__ void __launch_bounds__(256)
ngp_interp_kernel(const float* __restrict__ x,
                  const float2* __restrict__ tables,
                  float2* __restrict__ out)
{
    const int tid = blockIdx.x * 256 + threadIdx.x;   // tid = b*16 + l
    const int l = tid & (NL - 1);
    const int b = tid >> 4;

    const float res = c_res[l];

    // 16 lanes share the same point -> L1 broadcast, cheap.
    const float x0 = __ldg(x + b * 3 + 0);
    const float x1 = __ldg(x + b * 3 + 1);
    const float x2 = __ldg(x + b * 3 + 2);

    const float s0 = x0 * res, s1 = x1 * res, s2 = x2 * res;
    const float g0f = floorf(s0), g1f = floorf(s1), g2f = floorf(s2);
    const float f0 = s0 - g0f, f1 = s1 - g1f, f2 = s2 - g2f;

    const unsigned g0 = (unsigned)g0f;
    const unsigned g1 = (unsigned)g1f;
    const unsigned g2 = (unsigned)g2f;

    const unsigned P1 = 2654435761u, P2 = 805459861u;

    // Per-dimension hash contributions for border 0/1 (uint32 wraparound ok).
    const unsigned h0a = g0,            h0b = g0 + 1u;
    const unsigned h1a = g1 * P1,       h1b = (g1 + 1u) * P1;
    const unsigned h2a = g2 * P2,       h2b = (g2 + 1u) * P2;

    const float2* __restrict__ tab = tables + ((size_t)l << TBITS);

    unsigned idx[8];
    idx[0] = (h0a ^ h1a ^ h2a) & TMASK;
    idx[1] = (h0b ^ h1a ^ h2a) & TMASK;
    idx[2] = (h0a ^ h1b ^ h2a) & TMASK;
    idx[3] = (h0b ^ h1b ^ h2a) & TMASK;
    idx[4] = (h0a ^ h1a ^ h2b) & TMASK;
    idx[5] = (h0b ^ h1a ^ h2b) & TMASK;
    idx[6] = (h0a ^ h1b ^ h2b) & TMASK;
    idx[7] = (h0b ^ h1b ^ h2b) & TMASK;

    // Issue all 8 gathers up front (MLP=8 to hide L2 latency).
    float2 v[8];
#pragma unroll
    for (int i = 0; i < 8; i++) v[i] = __ldg(tab + idx[i]);

    // Trilinear weights: border=0 -> (1-f), border=1 -> f; bit v&1->dim0, v&2->dim1, v&4->dim2.
    const float w0a = 1.f - f0, w0b = f0;
    const float w1a = 1.f - f1, w1b = f1;
    const float w2a = 1.f - f2, w2b = f2;

    float w[8];
    w[0] = w0a * w1a * w2a;  w[1] = w0b * w1a * w2a;
    w[2] = w0a * w1b * w2a;  w[3] = w0b * w1b * w2a;
    w[4] = w0a * w1a * w2b;  w[5] = w0b * w1a * w2b;
    w[6] = w0a * w1b * w2b;  w[7] = w0b * w1b * w2b;

    float a0 = 0.f, a1 = 0.f;
#pragma unroll
    for (int i = 0; i < 8; i++) {
        a0 += w[i] * v[i].x;
        a1 += w[i] * v[i].y;
    }

    // out[b, l] as float2 -> index b*16 + l = tid. Fully coalesced.
    out[tid] = make_float2(a0, a1);
}

extern "C" void kernel_launch(void* const* d_in, const int* in_sizes, int n_in,
                              void* d_out, int out_size)
{
    // Robust input-order detection: x has 262144*3 = 786432 elements,
    // tables has 16*2^19*2 = 16777216 elements.
    const float* x   = (const float*)d_in[0];
    const float* tab = (const float*)d_in[1];
    if (n_in >= 2 && in_sizes[0] > in_sizes[1]) {
        const float* t = x; x = tab; tab = t;
    }

    const int total = NB * NL;                  // 4,194,304 threads
    ngp_interp_kernel<<<total / 256, 256>>>(x, (const float2*)tab, (float2*)d_out);
}

// round 3
// speedup vs baseline: 1.0739x; 1.0739x over previous
#include <cuda_runtime.h>
#include <stdint.h>

// Instant-NGP hash-grid interpolation encoding.
// B=262144 points, DIM=3, L=16 levels, T=19 (2^19-entry tables), F=2 features.
//
// Round-2 optimization (re-bench; infra failure last round): PRIMES[0]==1, so
// when g0 is even the two x-corners of every (dim1,dim2) combo sit at table
// indices idx and idx^1 -> one aligned float4 load instead of two float2
// gathers. Cuts L1tex wavefronts ~25% (the binding pipe at 84.7%).

#define NB   262144
#define NL   16
#define TBITS 19
#define TMASK ((1u << TBITS) - 1u)

__constant__ float c_res[NL] = {
    16.f, 20.f, 25.f, 32.f, 40.f, 50.f, 64.f, 80.f,
    101.f, 128.f, 161.f, 203.f, 256.f, 322.f, 406.f, 512.f
};

__global__ void __launch_bounds__(256)
ngp_interp_kernel(const float* __restrict__ x,
                  const float2* __restrict__ tables,
                  float2* __restrict__ out)
{
    const int tid = blockIdx.x * 256 + threadIdx.x;   // tid = b*16 + l
    const int l = tid & (NL - 1);
    const int b = tid >> 4;

    const float res = c_res[l];

    const float x0 = __ldg(x + b * 3 + 0);
    const float x1 = __ldg(x + b * 3 + 1);
    const float x2 = __ldg(x + b * 3 + 2);

    const float s0 = x0 * res, s1 = x1 * res, s2 = x2 * res;
    const float g0f = floorf(s0), g1f = floorf(s1), g2f = floorf(s2);
    const float f0 = s0 - g0f, f1 = s1 - g1f, f2 = s2 - g2f;

    const unsigned g0 = (unsigned)g0f;
    const unsigned g1 = (unsigned)g1f;
    const unsigned g2 = (unsigned)g2f;

    const unsigned P1 = 2654435761u, P2 = 805459861u;

    const unsigned h1a = g1 * P1, h1b = (g1 + 1u) * P1;
    const unsigned h2a = g2 * P2, h2b = (g2 + 1u) * P2;

    const float2* __restrict__ tab = tables + ((size_t)l << TBITS);

    // Weights: border=0 -> (1-f), border=1 -> f.
    const float w0a = 1.f - f0, w0b = f0;
    const float w1a = 1.f - f1, w1b = f1;
    const float w2a = 1.f - f2, w2b = f2;

    // Per-(dim1,dim2) combo: XOR of hash contributions and product weight.
    unsigned hy[4];
    hy[0] = h1a ^ h2a;  hy[1] = h1b ^ h2a;
    hy[2] = h1a ^ h2b;  hy[3] = h1b ^ h2b;

    float wp[4];
    wp[0] = w1a * w2a;  wp[1] = w1b * w2a;
    wp[2] = w1a * w2b;  wp[3] = w1b * w2b;

    float a0 = 0.f, a1 = 0.f;

    if ((g0 & 1u) == 0u) {
        // g0 even: x-corner pair = {idx, idx^1} -> aligned float4.
        const float4* __restrict__ tab4 = (const float4*)tab;

        unsigned idxA[4];
#pragma unroll
        for (int p = 0; p < 4; p++) idxA[p] = (g0 ^ hy[p]) & TMASK;

        float4 q[4];
#pragma unroll
        for (int p = 0; p < 4; p++) q[p] = __ldg(tab4 + (idxA[p] >> 1));

#pragma unroll
        for (int p = 0; p < 4; p++) {
            const bool hi = (idxA[p] & 1u) != 0u;
            // corner A = border0 (weight w0a) lives at idxA; B at idxA^1.
            const float vax = hi ? q[p].z : q[p].x;
            const float vay = hi ? q[p].w : q[p].y;
            const float vbx = hi ? q[p].x : q[p].z;
            const float vby = hi ? q[p].y : q[p].w;
            const float wA = w0a * wp[p];
            const float wB = w0b * wp[p];
            a0 += wA * vax + wB * vbx;
            a1 += wA * vay + wB * vby;
        }
    } else {
        // g0 odd: corners not adjacent -> 8 independent float2 gathers.
        const unsigned h0a = g0, h0b = g0 + 1u;

        unsigned idx[8];
#pragma unroll
        for (int p = 0; p < 4; p++) {
            idx[2 * p + 0] = (h0a ^ hy[p]) & TMASK;
            idx[2 * p + 1] = (h0b ^ hy[p]) & TMASK;
        }

        float2 v[8];
#pragma unroll
        for (int i = 0; i < 8; i++) v[i] = __ldg(tab + idx[i]);

#pragma unroll
        for (int p = 0; p < 4; p++) {
            const float wA = w0a * wp[p];
            const float wB = w0b * wp[p];
            a0 += wA * v[2 * p].x + wB * v[2 * p + 1].x;
            a1 += wA * v[2 * p].y + wB * v[2 * p + 1].y;
        }
    }

    out[tid] = make_float2(a0, a1);
}

extern "C" void kernel_launch(void* const* d_in, const int* in_sizes, int n_in,
                              void* d_out, int out_size)
{
    const float* x   = (const float*)d_in[0];
    const float* tab = (const float*)d_in[1];
    if (n_in >= 2 && in_sizes[0] > in_sizes[1]) {
        const float* t = x; x = tab; tab = t;
    }

    const int total = NB * NL;
    ngp_interp_kernel<<<total / 256, 256>>>(x, (const float2*)tab, (float2*)d_out);
}